// round 12
// baseline (speedup 1.0000x reference)
#include <cuda_runtime.h>
#include <cuda_bf16.h>
#include <math.h>

#define BB 64
#define SS 1024
#define DD 128
#define HH 20
#define GG 80   // 4*HH

typedef unsigned long long u64;

// ---------------- packed f32x2 helpers --------------------
__device__ __forceinline__ u64 pk2(float lo, float hi) {
    u64 r; asm("mov.b64 %0, {%1, %2};" : "=l"(r) : "f"(lo), "f"(hi)); return r;
}
__device__ __forceinline__ void upk2(u64 v, float& lo, float& hi) {
    asm("mov.b64 {%0, %1}, %2;" : "=f"(lo), "=f"(hi) : "l"(v));
}
__device__ __forceinline__ u64 ffma2(u64 a, u64 b, u64 c) {
    u64 d; asm("fma.rn.f32x2 %0, %1, %2, %3;" : "=l"(d) : "l"(a), "l"(b), "l"(c)); return d;
}
__device__ __forceinline__ float rcpa(float x) {
    float y; asm("rcp.approx.f32 %0, %1;" : "=f"(y) : "f"(x)); return y;
}
__device__ __forceinline__ float sigm(float x) {
    return rcpa(1.f + __expf(-x));
}
__device__ __forceinline__ float tanh_(float x) {          // 1 - 2/(e^2x+1)
    return fmaf(-2.f, rcpa(__expf(2.f * x) + 1.f), 1.f);
}

// ---------------- scratch (__device__ globals; no allocation) ----------------
// gpre stored unit-major: [(b*SS+t)*HH + u] = float4 (i_u, f_u, g_u, o_u)
__device__ float g_gpre[(size_t)BB * SS * GG];
__device__ float g_mu[(size_t)BB * SS];
__device__ float g_sigma[(size_t)BB * SS];

// Trivial probes: TWO placed first so ncu's profiled slot (4th launch,
// index 3) lands on k_lstm this round.
__global__ void k_probe() {}

// ============================================================================
// Kernel 1: gpre = x @ W_ih.T + (b_ih+b_hh). (unchanged, passing since R7)
// ============================================================================
#define GH 40
__global__ void __launch_bounds__(256) k_gates(const float* __restrict__ x,
                                               const float* __restrict__ Wih,
                                               const float* __restrict__ bih,
                                               const float* __restrict__ bhh) {
    __shared__ ulonglong2 Wsm[GH][17];    // 40 gates x 64 floats (+pad)
    __shared__ ulonglong2 xs[128][17];    // 128 rows x 64 floats (+pad)

    const int r0  = (blockIdx.x >> 1) * 128;
    const int gh  = (blockIdx.x & 1) * GH;
    const int tid = threadIdx.x;
    const int gq  = tid & 7;    // 5 gates: gh + gq*5 ..
    const int rq  = tid >> 3;   // 4 rows : rq*4 ..

    u64 acc[4][5];
    #pragma unroll
    for (int i = 0; i < 4; i++)
        #pragma unroll
        for (int g = 0; g < 5; g++) acc[i][g] = pk2(0.f, 0.f);

    #pragma unroll
    for (int kc = 0; kc < 2; kc++) {
        const ulonglong2* wg = (const ulonglong2*)Wih + (size_t)gh * 32 + kc * 16;
        #pragma unroll
        for (int i = tid; i < GH * 16; i += 256)
            Wsm[i >> 4][i & 15] = wg[(size_t)(i >> 4) * 32 + (i & 15)];
        const ulonglong2* xg = (const ulonglong2*)x + (size_t)r0 * 32 + kc * 16;
        #pragma unroll
        for (int i = tid; i < 128 * 16; i += 256)
            xs[i >> 4][i & 15] = xg[(size_t)(i >> 4) * 32 + (i & 15)];
        __syncthreads();

        #pragma unroll 4
        for (int dc = 0; dc < 16; dc++) {
            ulonglong2 xv[4];
            #pragma unroll
            for (int i = 0; i < 4; i++) xv[i] = xs[rq * 4 + i][dc];
            #pragma unroll
            for (int g = 0; g < 5; g++) {
                const ulonglong2 wv = Wsm[gq * 5 + g][dc];
                #pragma unroll
                for (int i = 0; i < 4; i++) {
                    acc[i][g] = ffma2(xv[i].x, wv.x, acc[i][g]);
                    acc[i][g] = ffma2(xv[i].y, wv.y, acc[i][g]);
                }
            }
        }
        __syncthreads();
    }

    #pragma unroll
    for (int g = 0; g < 5; g++) {
        const int gate = gh + gq * 5 + g;
        const int q = gate / HH, u = gate % HH;
        const float bias = __ldg(&bih[gate]) + __ldg(&bhh[gate]);
        #pragma unroll
        for (int i = 0; i < 4; i++) {
            float lo, hi; upk2(acc[i][g], lo, hi);
            const int r = r0 + rq * 4 + i;
            g_gpre[((size_t)r * HH + u) * 4 + q] = lo + hi + bias;
        }
    }
}

// ============================================================================
// Kernel 2: sequential LSTM per batch. Split ffma2 chains (depth 5+5)
// shorten the per-step critical path; otherwise the R7-proven structure.
// ============================================================================
__global__ void __launch_bounds__(32, 1) k_lstm(const float* __restrict__ Whh,
                                                const float* __restrict__ Wmu,
                                                const float* __restrict__ bmu,
                                                const float* __restrict__ Wsig,
                                                const float* __restrict__ bsig) {
    __shared__ float a_sm[SS];
    __shared__ float cst_sm[SS];

    const int b    = blockIdx.x;
    const int lane = threadIdx.x;
    const int lidx = lane < HH ? lane : 0;     // clamped load lane

    u64 w2[4][10];
    float b0 = 0.f, b1 = 0.f, b2 = 0.f, b3 = 0.f;

    if (lane < HH) {
        #pragma unroll
        for (int q = 0; q < 4; q++) {
            const u64* row = (const u64*)(Whh + (size_t)(q * HH + lane) * HH);
            #pragma unroll
            for (int m = 0; m < 10; m++) w2[q][m] = row[m];
        }
    } else if (lane == HH) {
        #pragma unroll
        for (int q = 0; q < 3; q++) {
            const u64* row = (const u64*)(Wmu + (size_t)q * HH);
            #pragma unroll
            for (int m = 0; m < 10; m++) w2[q][m] = row[m];
        }
        const u64* rs = (const u64*)Wsig;
        #pragma unroll
        for (int m = 0; m < 10; m++) w2[3][m] = rs[m];
        b0 = bmu[0]; b1 = bmu[1]; b2 = bmu[2]; b3 = bsig[0];
    } else {
        #pragma unroll
        for (int q = 0; q < 4; q++)
            #pragma unroll
            for (int m = 0; m < 10; m++) w2[q][m] = 0ull;
    }

    float h = 0.f, c = 0.f;
    const bool is_gate = (lane < HH);

    const float4* gp4 = (const float4*)g_gpre + (size_t)b * SS * HH;
    float4 pA = gp4[0 * HH + lidx];
    float4 pB = gp4[1 * HH + lidx];
    float4 pC = gp4[2 * HH + lidx];

    for (int t = 0; t <= SS; t++) {
        float g0 = is_gate ? pA.x : b0;
        float g1 = is_gate ? pA.y : b1;
        float g2 = is_gate ? pA.z : b2;
        float g3 = is_gate ? pA.w : b3;

        pA = pB; pB = pC;
        int tn = t + 3; tn = tn < SS ? tn : SS - 1;      // uniform clamp
        pC = gp4[(size_t)tn * HH + lidx];                // unconditional LDG

        // broadcast h_{t-1} as packed pairs (only lanes 0..19 sampled)
        u64 hp[10];
        #pragma unroll
        for (int m = 0; m < 10; m++) {
            const float lo = __shfl_sync(0xffffffffu, h, 2 * m);
            const float hi = __shfl_sync(0xffffffffu, h, 2 * m + 1);
            hp[m] = pk2(lo, hi);
        }

        // split chains: two 5-deep halves per gate, folded at the end
        u64 aA[4], aB[4];
        aA[0] = pk2(g0, 0.f); aA[1] = pk2(g1, 0.f);
        aA[2] = pk2(g2, 0.f); aA[3] = pk2(g3, 0.f);
        aB[0] = aB[1] = aB[2] = aB[3] = pk2(0.f, 0.f);
        #pragma unroll
        for (int m = 0; m < 5; m++) {
            #pragma unroll
            for (int q = 0; q < 4; q++) {
                aA[q] = ffma2(hp[m],     w2[q][m],     aA[q]);
                aB[q] = ffma2(hp[m + 5], w2[q][m + 5], aB[q]);
            }
        }
        { float lo, hi, lo2, hi2;
          upk2(aA[0], lo, hi); upk2(aB[0], lo2, hi2); g0 = (lo + hi) + (lo2 + hi2);
          upk2(aA[1], lo, hi); upk2(aB[1], lo2, hi2); g1 = (lo + hi) + (lo2 + hi2);
          upk2(aA[2], lo, hi); upk2(aB[2], lo2, hi2); g2 = (lo + hi) + (lo2 + hi2);
          upk2(aA[3], lo, hi); upk2(aB[3], lo2, hi2); g3 = (lo + hi) + (lo2 + hi2); }

        // lane HH projections of h_{t-1} (predicated stores only)
        if (lane == HH && t > 0) {
            const int tp = t - 1;
            a_sm[tp]   = fmaxf(g0, 0.f);
            cst_sm[tp] = fmaxf(g1, 0.f) * (1.f / SS)
                       + fmaxf(g2, 0.f) * ((float)tp + 1.f) * (1.f / SS);
            g_sigma[(size_t)b * SS + tp] = sigm(g3);
        }

        // LSTM update, all lanes unconditional (lanes >= HH produce unused h)
        const float ig = sigm(g0);
        const float fg = sigm(g1);
        const float gt = tanh_(g2);
        const float og = sigm(g3);
        c = fmaf(fg, c, ig * gt);
        h = og * tanh_(c);
    }
    __syncwarp();

    if (lane == 0) {                              // mu_t = a_t*mu_{t-1}+cst_t
        float m = 0.f;
        for (int t = 0; t < SS; t++) {
            m = fmaf(a_sm[t], m, cst_sm[t]);
            a_sm[t] = m;
        }
    }
    __syncwarp();
    for (int t = lane; t < SS; t += 32) g_mu[(size_t)b * SS + t] = a_sm[t];
}

// ============================================================================
// Kernel 3: fused w-gen + norm + triangular GEMM. TJ=64, 128 threads,
// thread = 8j x 8d. w stored DUPLICATED as u64 (w,w) in smem (stride 34 u64,
// broadcast rows conflict-free) so the packed operand is one LDS.64 —
// removes the ~32 MOV32/tt-pair that showed up as alu=13.8% in R11.
// smem = 16K (xs) + 17.4K (ws2) + 1K = 34.4KB.
// ============================================================================
#define TJ 64
#define TT 32

__global__ void __launch_bounds__(128) k_attn(const float* __restrict__ x,
                                              float* __restrict__ out) {
    __shared__ ulonglong2 xs[TT][32];            // 32 t x 128 floats (16KB)
    __shared__ u64 ws2[TJ][TT + 2];              // duplicated w (17.4KB)
    __shared__ float mus[TJ], nfac[TJ], ps[TJ], nrm[TJ];

    const int b   = blockIdx.y;
    const int jt  = (gridDim.x - 1) - blockIdx.x;    // heavy tiles first
    const int j0  = jt * TJ;
    const int tid = threadIdx.x;

    if (tid < TJ) {
        const int j   = j0 + tid;
        const float m = g_mu[(size_t)b * SS + j];
        const float s = g_sigma[(size_t)b * SS + j];
        const float s2 = fmaxf(s * s, 1e-30f);
        mus[tid]  = m;
        nfac[tid] = -0.5f * rcpa(s2);
        ps[tid]   = rcpa((float)(j + 1));
        nrm[tid]  = 0.f;
    }

    u64 acc[8][4];
    #pragma unroll
    for (int i = 0; i < 8; i++)
        #pragma unroll
        for (int d = 0; d < 4; d++) acc[i][d] = pk2(0.f, 0.f);

    const int ty = tid >> 4, tx = tid & 15;      // FMA-phase: j = ty + i*8
    const int sw = (tx >> 2) & 1;                // bank-swizzle swap bit
    const int cA = tx * 2 + sw;
    const int cB = tx * 2 + 1 - sw;
    const int jj = tid >> 1, tg = tid & 1;       // w-gen: 2 threads per j
    const ulonglong2* xb = (const ulonglong2*)(x + (size_t)b * SS * DD);

    const int ntiles = (j0 + TJ) / TT;
    __syncthreads();

    for (int tile = 0; tile < ntiles; tile++) {
        const int t0 = tile * TT;

        // stage x tile: 32 t x 128 floats = 32 x 32 ulonglong2, 128 threads
        #pragma unroll
        for (int i = tid; i < TT * 32; i += 128)
            xs[i >> 5][i & 31] = xb[(size_t)t0 * 32 + i];

        {   // generate w tile (+ accumulate ||w||^2): 16 t per thread
            const int   jg = j0 + jj;
            const float m  = mus[jj], nf = nfac[jj], p = ps[jj];
            float ssq = 0.f;
            #pragma unroll
            for (int s2 = 0; s2 < 16; s2++) {
                const int t = t0 + tg * 16 + s2;
                float w = 0.f;
                if (t <= jg) {
                    const float d = (float)t * p - m;
                    w = __expf(nf * d * d);
                }
                ws2[jj][tg * 16 + s2] = pk2(w, w);
                ssq = fmaf(w, w, ssq);
            }
            ssq += __shfl_xor_sync(0xffffffffu, ssq, 1);
            if (tg == 0) nrm[jj] += ssq;
        }
        __syncthreads();

        #pragma unroll 2
        for (int tt = 0; tt < TT; tt += 2) {
            const ulonglong2 xa0 = xs[tt][cA];
            const ulonglong2 xc0 = xs[tt][cB];
            const ulonglong2 xa1 = xs[tt + 1][cA];
            const ulonglong2 xc1 = xs[tt + 1][cB];
            #pragma unroll
            for (int i = 0; i < 8; i++) {
                const u64 w0 = ws2[ty + i * 8][tt];
                const u64 w1 = ws2[ty + i * 8][tt + 1];
                acc[i][0] = ffma2(w0, xa0.x, acc[i][0]);
                acc[i][1] = ffma2(w0, xa0.y, acc[i][1]);
                acc[i][2] = ffma2(w0, xc0.x, acc[i][2]);
                acc[i][3] = ffma2(w0, xc0.y, acc[i][3]);
                acc[i][0] = ffma2(w1, xa1.x, acc[i][0]);
                acc[i][1] = ffma2(w1, xa1.y, acc[i][1]);
                acc[i][2] = ffma2(w1, xc1.x, acc[i][2]);
                acc[i][3] = ffma2(w1, xc1.y, acc[i][3]);
            }
        }
        __syncthreads();
    }

    #pragma unroll
    for (int i = 0; i < 8; i++) {
        const int jl = ty + i * 8;
        const float inv = 1.f / fmaxf(sqrtf(nrm[jl]), 1e-12f);
        float v[8];
        upk2(acc[i][0], v[0], v[1]);
        upk2(acc[i][1], v[2], v[3]);
        upk2(acc[i][2], v[4], v[5]);
        upk2(acc[i][3], v[6], v[7]);
        float4 oA = make_float4(v[0] * inv, v[1] * inv, v[2] * inv, v[3] * inv);
        float4 oB = make_float4(v[4] * inv, v[5] * inv, v[6] * inv, v[7] * inv);
        float4 olo = sw ? oB : oA;     // un-swap: oA holds column cA
        float4 ohi = sw ? oA : oB;
        float4* op = (float4*)(out + ((size_t)b * SS + j0 + jl) * DD + tx * 8);
        op[0] = olo;
        op[1] = ohi;
    }
}

// ============================================================================
extern "C" void kernel_launch(void* const* d_in, const int* in_sizes, int n_in,
                              void* d_out, int out_size) {
    const float* x    = (const float*)d_in[0];
    const float* Wih  = (const float*)d_in[1];
    const float* Whh  = (const float*)d_in[2];
    const float* bih  = (const float*)d_in[3];
    const float* bhh  = (const float*)d_in[4];
    const float* Wmu  = (const float*)d_in[5];
    const float* bmu  = (const float*)d_in[6];
    const float* Wsig = (const float*)d_in[7];
    const float* bsig = (const float*)d_in[8];
    float* out = (float*)d_out;

    k_probe<<<1, 32>>>();                      // slot-steer: profiled launch
    k_probe<<<1, 32>>>();                      // (index 3) lands on k_lstm
    k_gates<<<dim3((BB * SS / 128) * 2), 256>>>(x, Wih, bih, bhh);
    k_lstm<<<BB, 32>>>(Whh, Wmu, bmu, Wsig, bsig);
    k_attn<<<dim3(SS / TJ, BB), 128>>>(x, out);
}

// round 14
// speedup vs baseline: 1.1547x; 1.1547x over previous
#include <cuda_runtime.h>
#include <cuda_bf16.h>
#include <math.h>

#define BB 64
#define SS 1024
#define DD 128
#define HH 20
#define GG 80   // 4*HH

typedef unsigned long long u64;

// ---------------- packed f32x2 + math helpers --------------------
__device__ __forceinline__ u64 pk2(float lo, float hi) {
    u64 r; asm("mov.b64 %0, {%1, %2};" : "=l"(r) : "f"(lo), "f"(hi)); return r;
}
__device__ __forceinline__ void upk2(u64 v, float& lo, float& hi) {
    asm("mov.b64 {%0, %1}, %2;" : "=f"(lo), "=f"(hi) : "l"(v));
}
__device__ __forceinline__ u64 ffma2(u64 a, u64 b, u64 c) {
    u64 d; asm("fma.rn.f32x2 %0, %1, %2, %3;" : "=l"(d) : "l"(a), "l"(b), "l"(c)); return d;
}
__device__ __forceinline__ float rcpa(float x) {
    float y; asm("rcp.approx.f32 %0, %1;" : "=f"(y) : "f"(x)); return y;
}
__device__ __forceinline__ float sigm(float x) {           // exact-path sigmoid
    return rcpa(1.f + __expf(-x));
}
__device__ __forceinline__ float tanha(float x) {          // MUFU.TANH
    float y; asm("tanh.approx.f32 %0, %1;" : "=f"(y) : "f"(x)); return y;
}
__device__ __forceinline__ float sigm_t(float x) {         // 1 MUFU sigmoid
    return fmaf(0.5f, tanha(0.5f * x), 0.5f);
}

// ---------------- scratch (__device__ globals; no allocation) ----------------
// gpre stored unit-major: [(b*SS+t)*HH + u] = float4 (i_u, f_u, g_u, o_u)
__device__ float g_gpre[(size_t)BB * SS * GG];
__device__ float g_mu[(size_t)BB * SS];
__device__ float g_sigma[(size_t)BB * SS];

// Trivial probes: TWO placed first so ncu's profiled slot (4th launch,
// index 3) stays on k_lstm — measuring the MUFU.TANH change directly.
__global__ void k_probe() {}

// ============================================================================
// Kernel 1: gpre = x @ W_ih.T + (b_ih+b_hh). (unchanged, passing since R7)
// ============================================================================
#define GH 40
__global__ void __launch_bounds__(256) k_gates(const float* __restrict__ x,
                                               const float* __restrict__ Wih,
                                               const float* __restrict__ bih,
                                               const float* __restrict__ bhh) {
    __shared__ ulonglong2 Wsm[GH][17];    // 40 gates x 64 floats (+pad)
    __shared__ ulonglong2 xs[128][17];    // 128 rows x 64 floats (+pad)

    const int r0  = (blockIdx.x >> 1) * 128;
    const int gh  = (blockIdx.x & 1) * GH;
    const int tid = threadIdx.x;
    const int gq  = tid & 7;    // 5 gates: gh + gq*5 ..
    const int rq  = tid >> 3;   // 4 rows : rq*4 ..

    u64 acc[4][5];
    #pragma unroll
    for (int i = 0; i < 4; i++)
        #pragma unroll
        for (int g = 0; g < 5; g++) acc[i][g] = pk2(0.f, 0.f);

    #pragma unroll
    for (int kc = 0; kc < 2; kc++) {
        const ulonglong2* wg = (const ulonglong2*)Wih + (size_t)gh * 32 + kc * 16;
        #pragma unroll
        for (int i = tid; i < GH * 16; i += 256)
            Wsm[i >> 4][i & 15] = wg[(size_t)(i >> 4) * 32 + (i & 15)];
        const ulonglong2* xg = (const ulonglong2*)x + (size_t)r0 * 32 + kc * 16;
        #pragma unroll
        for (int i = tid; i < 128 * 16; i += 256)
            xs[i >> 4][i & 15] = xg[(size_t)(i >> 4) * 32 + (i & 15)];
        __syncthreads();

        #pragma unroll 4
        for (int dc = 0; dc < 16; dc++) {
            ulonglong2 xv[4];
            #pragma unroll
            for (int i = 0; i < 4; i++) xv[i] = xs[rq * 4 + i][dc];
            #pragma unroll
            for (int g = 0; g < 5; g++) {
                const ulonglong2 wv = Wsm[gq * 5 + g][dc];
                #pragma unroll
                for (int i = 0; i < 4; i++) {
                    acc[i][g] = ffma2(xv[i].x, wv.x, acc[i][g]);
                    acc[i][g] = ffma2(xv[i].y, wv.y, acc[i][g]);
                }
            }
        }
        __syncthreads();
    }

    #pragma unroll
    for (int g = 0; g < 5; g++) {
        const int gate = gh + gq * 5 + g;
        const int q = gate / HH, u = gate % HH;
        const float bias = __ldg(&bih[gate]) + __ldg(&bhh[gate]);
        #pragma unroll
        for (int i = 0; i < 4; i++) {
            float lo, hi; upk2(acc[i][g], lo, hi);
            const int r = r0 + rq * 4 + i;
            g_gpre[((size_t)r * HH + u) * 4 + q] = lo + hi + bias;
        }
    }
}

// ============================================================================
// Kernel 2: sequential LSTM per batch. R11 chain structure (10-deep, the
// measured-better shape) + MUFU.TANH nonlinearities: 10 MUFU/step -> 5.
// sigma path stays EXACT (w=exp(-d^2/2s^2) amplifies sigma errors ~10x).
// ============================================================================
__global__ void __launch_bounds__(32, 1) k_lstm(const float* __restrict__ Whh,
                                                const float* __restrict__ Wmu,
                                                const float* __restrict__ bmu,
                                                const float* __restrict__ Wsig,
                                                const float* __restrict__ bsig) {
    __shared__ float a_sm[SS];
    __shared__ float cst_sm[SS];

    const int b    = blockIdx.x;
    const int lane = threadIdx.x;
    const int lidx = lane < HH ? lane : 0;     // clamped load lane

    u64 w2[4][10];
    float b0 = 0.f, b1 = 0.f, b2 = 0.f, b3 = 0.f;

    if (lane < HH) {
        #pragma unroll
        for (int q = 0; q < 4; q++) {
            const u64* row = (const u64*)(Whh + (size_t)(q * HH + lane) * HH);
            #pragma unroll
            for (int m = 0; m < 10; m++) w2[q][m] = row[m];
        }
    } else if (lane == HH) {
        #pragma unroll
        for (int q = 0; q < 3; q++) {
            const u64* row = (const u64*)(Wmu + (size_t)q * HH);
            #pragma unroll
            for (int m = 0; m < 10; m++) w2[q][m] = row[m];
        }
        const u64* rs = (const u64*)Wsig;
        #pragma unroll
        for (int m = 0; m < 10; m++) w2[3][m] = rs[m];
        b0 = bmu[0]; b1 = bmu[1]; b2 = bmu[2]; b3 = bsig[0];
    } else {
        #pragma unroll
        for (int q = 0; q < 4; q++)
            #pragma unroll
            for (int m = 0; m < 10; m++) w2[q][m] = 0ull;
    }

    float h = 0.f, c = 0.f;
    const bool is_gate = (lane < HH);

    const float4* gp4 = (const float4*)g_gpre + (size_t)b * SS * HH;
    float4 pA = gp4[0 * HH + lidx];
    float4 pB = gp4[1 * HH + lidx];
    float4 pC = gp4[2 * HH + lidx];

    for (int t = 0; t <= SS; t++) {
        float g0 = is_gate ? pA.x : b0;
        float g1 = is_gate ? pA.y : b1;
        float g2 = is_gate ? pA.z : b2;
        float g3 = is_gate ? pA.w : b3;

        pA = pB; pB = pC;
        int tn = t + 3; tn = tn < SS ? tn : SS - 1;      // uniform clamp
        pC = gp4[(size_t)tn * HH + lidx];                // unconditional LDG

        // broadcast h_{t-1} as packed pairs (only lanes 0..19 sampled)
        u64 hp[10];
        #pragma unroll
        for (int m = 0; m < 10; m++) {
            const float lo = __shfl_sync(0xffffffffu, h, 2 * m);
            const float hi = __shfl_sync(0xffffffffu, h, 2 * m + 1);
            hp[m] = pk2(lo, hi);
        }

        u64 a0 = pk2(g0, 0.f), a1 = pk2(g1, 0.f);
        u64 a2 = pk2(g2, 0.f), a3 = pk2(g3, 0.f);
        #pragma unroll
        for (int m = 0; m < 10; m++) {
            a0 = ffma2(hp[m], w2[0][m], a0);
            a1 = ffma2(hp[m], w2[1][m], a1);
            a2 = ffma2(hp[m], w2[2][m], a2);
            a3 = ffma2(hp[m], w2[3][m], a3);
        }
        { float lo, hi;
          upk2(a0, lo, hi); g0 = lo + hi;
          upk2(a1, lo, hi); g1 = lo + hi;
          upk2(a2, lo, hi); g2 = lo + hi;
          upk2(a3, lo, hi); g3 = lo + hi; }

        // lane HH projections of h_{t-1}; sigma stays EXACT
        if (lane == HH && t > 0) {
            const int tp = t - 1;
            a_sm[tp]   = fmaxf(g0, 0.f);
            cst_sm[tp] = fmaxf(g1, 0.f) * (1.f / SS)
                       + fmaxf(g2, 0.f) * ((float)tp + 1.f) * (1.f / SS);
            g_sigma[(size_t)b * SS + tp] = sigm(g3);
        }

        // LSTM update via MUFU.TANH (all lanes; lanes >= HH's h unused)
        const float ig = sigm_t(g0);
        const float fg = sigm_t(g1);
        const float gt = tanha(g2);
        const float og = sigm_t(g3);
        c = fmaf(fg, c, ig * gt);
        h = og * tanha(c);
    }
    __syncwarp();

    if (lane == 0) {                              // mu_t = a_t*mu_{t-1}+cst_t
        float m = 0.f;
        for (int t = 0; t < SS; t++) {
            m = fmaf(a_sm[t], m, cst_sm[t]);
            a_sm[t] = m;
        }
    }
    __syncwarp();
    for (int t = lane; t < SS; t += 32) g_mu[(size_t)b * SS + t] = a_sm[t];
}

// ============================================================================
// Kernel 3: fused w-gen + norm + triangular GEMM. (unchanged R12 winner:
// TJ=64, 128 threads, 8j x 8d, w duplicated u64 in smem -> one LDS.64.)
// ============================================================================
#define TJ 64
#define TT 32

__global__ void __launch_bounds__(128) k_attn(const float* __restrict__ x,
                                              float* __restrict__ out) {
    __shared__ ulonglong2 xs[TT][32];            // 32 t x 128 floats (16KB)
    __shared__ u64 ws2[TJ][TT + 2];              // duplicated w (17.4KB)
    __shared__ float mus[TJ], nfac[TJ], ps[TJ], nrm[TJ];

    const int b   = blockIdx.y;
    const int jt  = (gridDim.x - 1) - blockIdx.x;    // heavy tiles first
    const int j0  = jt * TJ;
    const int tid = threadIdx.x;

    if (tid < TJ) {
        const int j   = j0 + tid;
        const float m = g_mu[(size_t)b * SS + j];
        const float s = g_sigma[(size_t)b * SS + j];
        const float s2 = fmaxf(s * s, 1e-30f);
        mus[tid]  = m;
        nfac[tid] = -0.5f * rcpa(s2);
        ps[tid]   = rcpa((float)(j + 1));
        nrm[tid]  = 0.f;
    }

    u64 acc[8][4];
    #pragma unroll
    for (int i = 0; i < 8; i++)
        #pragma unroll
        for (int d = 0; d < 4; d++) acc[i][d] = pk2(0.f, 0.f);

    const int ty = tid >> 4, tx = tid & 15;      // FMA-phase: j = ty + i*8
    const int sw = (tx >> 2) & 1;                // bank-swizzle swap bit
    const int cA = tx * 2 + sw;
    const int cB = tx * 2 + 1 - sw;
    const int jj = tid >> 1, tg = tid & 1;       // w-gen: 2 threads per j
    const ulonglong2* xb = (const ulonglong2*)(x + (size_t)b * SS * DD);

    const int ntiles = (j0 + TJ) / TT;
    __syncthreads();

    for (int tile = 0; tile < ntiles; tile++) {
        const int t0 = tile * TT;

        // stage x tile: 32 t x 128 floats = 32 x 32 ulonglong2, 128 threads
        #pragma unroll
        for (int i = tid; i < TT * 32; i += 128)
            xs[i >> 5][i & 31] = xb[(size_t)t0 * 32 + i];

        {   // generate w tile (+ accumulate ||w||^2): 16 t per thread
            const int   jg = j0 + jj;
            const float m  = mus[jj], nf = nfac[jj], p = ps[jj];
            float ssq = 0.f;
            #pragma unroll
            for (int s2 = 0; s2 < 16; s2++) {
                const int t = t0 + tg * 16 + s2;
                float w = 0.f;
                if (t <= jg) {
                    const float d = (float)t * p - m;
                    w = __expf(nf * d * d);
                }
                ws2[jj][tg * 16 + s2] = pk2(w, w);
                ssq = fmaf(w, w, ssq);
            }
            ssq += __shfl_xor_sync(0xffffffffu, ssq, 1);
            if (tg == 0) nrm[jj] += ssq;
        }
        __syncthreads();

        #pragma unroll 2
        for (int tt = 0; tt < TT; tt += 2) {
            const ulonglong2 xa0 = xs[tt][cA];
            const ulonglong2 xc0 = xs[tt][cB];
            const ulonglong2 xa1 = xs[tt + 1][cA];
            const ulonglong2 xc1 = xs[tt + 1][cB];
            #pragma unroll
            for (int i = 0; i < 8; i++) {
                const u64 w0 = ws2[ty + i * 8][tt];
                const u64 w1 = ws2[ty + i * 8][tt + 1];
                acc[i][0] = ffma2(w0, xa0.x, acc[i][0]);
                acc[i][1] = ffma2(w0, xa0.y, acc[i][1]);
                acc[i][2] = ffma2(w0, xc0.x, acc[i][2]);
                acc[i][3] = ffma2(w0, xc0.y, acc[i][3]);
                acc[i][0] = ffma2(w1, xa1.x, acc[i][0]);
                acc[i][1] = ffma2(w1, xa1.y, acc[i][1]);
                acc[i][2] = ffma2(w1, xc1.x, acc[i][2]);
                acc[i][3] = ffma2(w1, xc1.y, acc[i][3]);
            }
        }
        __syncthreads();
    }

    #pragma unroll
    for (int i = 0; i < 8; i++) {
        const int jl = ty + i * 8;
        const float inv = 1.f / fmaxf(sqrtf(nrm[jl]), 1e-12f);
        float v[8];
        upk2(acc[i][0], v[0], v[1]);
        upk2(acc[i][1], v[2], v[3]);
        upk2(acc[i][2], v[4], v[5]);
        upk2(acc[i][3], v[6], v[7]);
        float4 oA = make_float4(v[0] * inv, v[1] * inv, v[2] * inv, v[3] * inv);
        float4 oB = make_float4(v[4] * inv, v[5] * inv, v[6] * inv, v[7] * inv);
        float4 olo = sw ? oB : oA;     // un-swap: oA holds column cA
        float4 ohi = sw ? oA : oB;
        float4* op = (float4*)(out + ((size_t)b * SS + j0 + jl) * DD + tx * 8);
        op[0] = olo;
        op[1] = ohi;
    }
}

// ============================================================================
extern "C" void kernel_launch(void* const* d_in, const int* in_sizes, int n_in,
                              void* d_out, int out_size) {
    const float* x    = (const float*)d_in[0];
    const float* Wih  = (const float*)d_in[1];
    const float* Whh  = (const float*)d_in[2];
    const float* bih  = (const float*)d_in[3];
    const float* bhh  = (const float*)d_in[4];
    const float* Wmu  = (const float*)d_in[5];
    const float* bmu  = (const float*)d_in[6];
    const float* Wsig = (const float*)d_in[7];
    const float* bsig = (const float*)d_in[8];
    float* out = (float*)d_out;

    k_probe<<<1, 32>>>();                      // slot-steer: profiled launch
    k_probe<<<1, 32>>>();                      // (index 3) lands on k_lstm
    k_gates<<<dim3((BB * SS / 128) * 2), 256>>>(x, Wih, bih, bhh);
    k_lstm<<<BB, 32>>>(Whh, Wmu, bmu, Wsig, bsig);
    k_attn<<<dim3(SS / TJ, BB), 128>>>(x, out);
}